// round 10
// baseline (speedup 1.0000x reference)
#include <cuda_runtime.h>
#include <cuda_fp16.h>
#include <cstdint>

#define BATCH 32
#define CIN 128
#define OUTC 128
#define HIDDEN 32
#define TEMP 31.0f
#define HW 3136
#define PIXB 128
#define NPB 25
#define NPBLK 98

// dynamic smem: bias @0, A halo (348 rows * 128B) @1024, B 2x32KB (2 taps each)
#define SM_A 1024
#define A_ROWS 348
#define A_BYTES (A_ROWS * 128)       // 44544
#define SM_B (SM_A + A_BYTES)        // 45568
#define SM_TOT (SM_B + 2 * 32768)    // 111104  (108.5KB -> 2 CTAs/SM)

__device__ float g_attn[BATCH][2];
__device__ float g_part[BATCH * CIN * NPBLK];
__device__ __align__(16) __half g_xh[(size_t)BATCH * HW * CIN];          // NHWC
__device__ __align__(16) __half g_wagg[(size_t)BATCH * 9 * OUTC * CIN];  // [b][t][o][c]

// swizzle for 128B rows
#define SWZ(o) ((o) ^ (((o) >> 3) & 0x70))

__device__ __forceinline__ uint32_t smem_u32(const void* p) {
    uint32_t a;
    asm("{ .reg .u64 t; cvta.to.shared.u64 t, %1; cvt.u32.u64 %0, t; }" : "=r"(a) : "l"(p));
    return a;
}
__device__ __forceinline__ void ldm4(uint32_t* r, uint32_t addr) {
    asm volatile("ldmatrix.sync.aligned.m8n8.x4.shared.b16 {%0,%1,%2,%3}, [%4];"
                 : "=r"(r[0]), "=r"(r[1]), "=r"(r[2]), "=r"(r[3]) : "r"(addr));
}
__device__ __forceinline__ void mma16816(float* c, const uint32_t* a, const uint32_t* b) {
    asm volatile("mma.sync.aligned.m16n8k16.row.col.f32.f16.f16.f32 "
                 "{%0,%1,%2,%3}, {%4,%5,%6,%7}, {%8,%9}, {%0,%1,%2,%3};"
                 : "+f"(c[0]), "+f"(c[1]), "+f"(c[2]), "+f"(c[3])
                 : "r"(a[0]), "r"(a[1]), "r"(a[2]), "r"(a[3]), "r"(b[0]), "r"(b[1]));
}
__device__ __forceinline__ void cpasync16(uint32_t dst, const void* src, uint32_t srcsz) {
    asm volatile("cp.async.cg.shared.global [%0], [%1], 16, %2;"
                 :: "r"(dst), "l"(src), "r"(srcsz) : "memory");
}
#define CP_COMMIT() asm volatile("cp.async.commit_group;" ::: "memory")
#define CP_WAIT0()  asm volatile("cp.async.wait_group 0;" ::: "memory")

// ---- prolog 1: NCHW f32 -> NHWC fp16 (half2 stores) + pooling partials ----
__global__ void convx_kernel(const float* __restrict__ x) {
    __shared__ float t[64][33];
    const int b = blockIdx.z, c0 = blockIdx.y * 64, p0 = blockIdx.x * 32;
    const int tx = threadIdx.x, ty = threadIdx.y;   // (32, 8)
    #pragma unroll
    for (int k = 0; k < 8; ++k)
        t[ty + 8 * k][tx] = x[((size_t)b * CIN + c0 + ty + 8 * k) * HW + p0 + tx];
    __syncthreads();
    __half2* xh2 = (__half2*)g_xh;
    #pragma unroll
    for (int kk = 0; kk < 4; ++kk) {
        int p = ty + 8 * kk;
        xh2[((size_t)b * HW + p0 + p) * 64 + (c0 >> 1) + tx] =
            __floats2half2_rn(t[2 * tx][p], t[2 * tx + 1][p]);
    }
    #pragma unroll
    for (int k = 0; k < 8; ++k) {
        int c = ty * 8 + k;
        float s = t[c][tx];
        #pragma unroll
        for (int o = 16; o; o >>= 1) s += __shfl_xor_sync(0xffffffffu, s, o);
        if (tx == 0) g_part[((size_t)b * CIN + c0 + c) * NPBLK + blockIdx.x] = s;
    }
}

// ---- prolog 2: reduce partials -> mlp -> softmax ----
__global__ void mlp_kernel(const float* __restrict__ fc1_w, const float* __restrict__ fc2_w) {
    const int b = blockIdx.x, tid = threadIdx.x;
    __shared__ float pooled[CIN], hid[HIDDEN], logits[2];
    if (tid < CIN) {
        const float* pp = g_part + (size_t)(b * CIN + tid) * NPBLK;
        float s = 0.f;
        for (int i = 0; i < NPBLK; ++i) s += pp[i];
        pooled[tid] = s * (1.0f / (float)HW);
    }
    __syncthreads();
    if (tid < HIDDEN) {
        float h = 0.f;
        for (int c = 0; c < CIN; ++c) h += pooled[c] * fc1_w[tid * CIN + c];
        hid[tid] = fmaxf(h, 0.f);
    }
    __syncthreads();
    if (tid < 2) {
        float l = 0.f;
        for (int j = 0; j < HIDDEN; ++j) l += hid[j] * fc2_w[tid * HIDDEN + j];
        logits[tid] = l;
    }
    __syncthreads();
    if (tid == 0) {
        float l0 = logits[0] / TEMP, l1 = logits[1] / TEMP;
        float m = fmaxf(l0, l1), e0 = __expf(l0 - m), e1 = __expf(l1 - m);
        float inv = 1.0f / (e0 + e1);
        g_attn[b][0] = e0 * inv;
        g_attn[b][1] = e1 * inv;
    }
}

// ---- prolog 3: weight aggregation -> fp16 [b][t][o][c] (half2 stores) ----
__global__ void aggw_kernel(const float* __restrict__ cw, const float* __restrict__ dw) {
    __shared__ float cs[1152], ds[1152];
    const int o = blockIdx.x, tid = threadIdx.x;
    for (int e = tid; e < 1152; e += 256) {
        cs[e] = cw[(size_t)o * 1152 + e];
        ds[e] = dw[(size_t)o * 1152 + e];
    }
    __syncthreads();
    const int c2 = tid & 63, q = tid >> 6;
    __half2* wg2 = (__half2*)g_wagg;
    for (int bt = q * 72; bt < (q + 1) * 72; ++bt) {
        int b = bt / 9, t = bt - b * 9;
        float a0 = g_attn[b][0], a1 = g_attn[b][1];
        float v0 = a0 * cs[(2 * c2) * 9 + t] + a1 * ds[(2 * c2) * 9 + t];
        float v1 = a0 * cs[(2 * c2 + 1) * 9 + t] + a1 * ds[(2 * c2 + 1) * 9 + t];
        wg2[(((size_t)b * 9 + t) * OUTC + o) * 64 + c2] = __floats2half2_rn(v0, v1);
    }
}

// ---- main conv: HMMA implicit GEMM, 2 taps per pipeline stage ----
__global__ void __launch_bounds__(256, 2)
conv_kernel(const float* __restrict__ cb, const float* __restrict__ db,
            float* __restrict__ out) {
    extern __shared__ char sm[];
    const uint32_t smb = smem_u32(sm);
    const int tid = threadIdx.x, wid = tid >> 5, lane = tid & 31;
    const int wm = wid & 3, wn = wid >> 2;               // 4 m-warps x 2 n-warps
    const int b = blockIdx.y, pbase = blockIdx.x * PIXB;
    const int h0 = pbase / 56;

    float* bias = (float*)sm;
    if (tid < OUTC) bias[tid] = g_attn[b][0] * cb[tid] + g_attn[b][1] * db[tid];

    const __half* xb = g_xh + (size_t)b * HW * CIN;
    const __half* wb = g_wagg + (size_t)b * 9 * OUTC * CIN;

    int hh[2], ww[2];
    #pragma unroll
    for (int mi = 0; mi < 2; ++mi) {
        int p = pbase + wm * 32 + mi * 16 + (lane & 15);
        if (p >= HW) p = HW - 1;
        hh[mi] = p / 56;
        ww[mi] = p - hh[mi] * 56;
    }

    float acc[2][8][4];
    #pragma unroll
    for (int mi = 0; mi < 2; ++mi)
        #pragma unroll
        for (int ni = 0; ni < 8; ++ni)
            #pragma unroll
            for (int e = 0; e < 4; ++e) acc[mi][ni][e] = 0.f;

    uint32_t brow[4];
    #pragma unroll
    for (int nb = 0; nb < 4; ++nb)
        brow[nb] = (uint32_t)(wn * 64 + nb * 16 + (lane & 15)) * 128;
    const uint32_t bxr = (uint32_t)(lane & 7) << 4;
    const uint32_t ksub = (uint32_t)((lane >> 4) << 4);

    // --- initial stage: A half0 + B stage 0 (taps 0,1 of half0) ---
    for (int e = tid; e < A_ROWS * 8; e += 256) {
        int rr = e >> 3, ch = e & 7;
        int ih = h0 - 1 + rr / 58, iw = rr % 58 - 1;
        bool ok = ((unsigned)ih < 56u) && ((unsigned)iw < 56u);
        const void* src = xb + (ok ? ((size_t)(ih * 56 + iw) * CIN + ch * 8) : 0);
        cpasync16(smb + SM_A + SWZ((uint32_t)rr * 128 + ch * 16), src, ok ? 16u : 0u);
    }
    for (int e = tid; e < 2 * 1024; e += 256) {
        int j = e >> 10, r = (e & 1023) >> 3, ch = e & 7;
        cpasync16(smb + SM_B + (uint32_t)j * 16384 + SWZ((uint32_t)r * 128 + ch * 16),
                  wb + ((size_t)j * OUTC + r) * CIN + ch * 8, 16u);
    }
    CP_COMMIT();
    CP_WAIT0();
    __syncthreads();

    // 10 stages: s = hf*5 + k; stage k<4 covers taps {2k,2k+1}, k=4 covers tap 8
    for (int s = 0; s < 10; ++s) {
        const int hf = s / 5, k = s - hf * 5;
        const int ntaps = (k < 4) ? 2 : 1;

        // prefetch next stage's B into alternate buffer
        if (s < 9) {
            const int sn = s + 1, hfn = sn / 5, kn = sn - hfn * 5;
            const int ntn = (kn < 4) ? 2 : 1, t0n = 2 * kn;
            const __half* wsrc = wb + (size_t)hfn * 64;
            uint32_t buf = smb + SM_B + (uint32_t)((sn & 1) * 32768);
            for (int e = tid; e < ntn * 1024; e += 256) {
                int j = e >> 10, r = (e & 1023) >> 3, ch = e & 7;
                cpasync16(buf + (uint32_t)j * 16384 + SWZ((uint32_t)r * 128 + ch * 16),
                          wsrc + ((size_t)(t0n + j) * OUTC + r) * CIN + ch * 8, 16u);
            }
            CP_COMMIT();
        }

        // compute the taps in this stage
        for (int j = 0; j < ntaps; ++j) {
            const int t = 2 * k + j;
            const int di = t / 3, dj = t - di * 3;
            uint32_t abase[2], axr[2];
            #pragma unroll
            for (int mi = 0; mi < 2; ++mi) {
                uint32_t rr = (uint32_t)((hh[mi] - h0 + di) * 58 + ww[mi] + dj);
                abase[mi] = smb + SM_A + rr * 128;
                axr[mi] = (rr & 7) << 4;
            }
            const uint32_t bbuf = smb + SM_B + (uint32_t)((s & 1) * 32768)
                                + (uint32_t)j * 16384;
            #pragma unroll
            for (int ks = 0; ks < 4; ++ks) {
                const uint32_t kb = (uint32_t)ks * 32 + ksub;
                uint32_t a[2][4], bf[8][2];
                #pragma unroll
                for (int mi = 0; mi < 2; ++mi)
                    ldm4(a[mi], abase[mi] + (kb ^ axr[mi]));
                #pragma unroll
                for (int nb = 0; nb < 4; ++nb) {
                    uint32_t r[4];
                    ldm4(r, bbuf + brow[nb] + (kb ^ bxr));
                    bf[nb * 2][0] = r[0]; bf[nb * 2][1] = r[2];
                    bf[nb * 2 + 1][0] = r[1]; bf[nb * 2 + 1][1] = r[3];
                }
                #pragma unroll
                for (int mi = 0; mi < 2; ++mi)
                    #pragma unroll
                    for (int ni = 0; ni < 8; ++ni)
                        mma16816(acc[mi][ni], a[mi], bf[ni]);
            }
        }

        if (s == 4) {
            // restage A for channel half 1 (all half-0 reads done)
            __syncthreads();
            for (int e = tid; e < A_ROWS * 8; e += 256) {
                int rr = e >> 3, ch = e & 7;
                int ih = h0 - 1 + rr / 58, iw = rr % 58 - 1;
                bool ok = ((unsigned)ih < 56u) && ((unsigned)iw < 56u);
                const void* src = xb + (ok ? ((size_t)(ih * 56 + iw) * CIN + 64 + ch * 8) : 0);
                cpasync16(smb + SM_A + SWZ((uint32_t)rr * 128 + ch * 16), src, ok ? 16u : 0u);
            }
            CP_COMMIT();
        }
        if (s < 9) {
            CP_WAIT0();
            __syncthreads();
        }
    }

    // ---- epilogue: stage C through smem (overlays A/B), coalesced STG ----
    float* csm = (float*)(sm + SM_A);          // [128 oc][132 px floats]
    float* ob = out + (size_t)b * OUTC * HW;
    __syncthreads();
    #pragma unroll
    for (int mi = 0; mi < 2; ++mi) {
        const int prl = wm * 32 + mi * 16 + (lane >> 2);
        #pragma unroll
        for (int ni = 0; ni < 8; ++ni) {
            const int ocl = wn * 64 + ni * 8 + (lane & 3) * 2;
            csm[ocl * 132 + prl]           = acc[mi][ni][0];
            csm[(ocl + 1) * 132 + prl]     = acc[mi][ni][1];
            csm[ocl * 132 + prl + 8]       = acc[mi][ni][2];
            csm[(ocl + 1) * 132 + prl + 8] = acc[mi][ni][3];
        }
    }
    __syncthreads();
    #pragma unroll
    for (int i = 0; i < 16; ++i) {
        int idx = tid + i * 256;               // ocl*32 + px4
        int ocl = idx >> 5, px4 = idx & 31;
        int pix = pbase + px4 * 4;
        if (pix < HW) {
            float4 v = *(float4*)&csm[ocl * 132 + px4 * 4];
            float bb = bias[ocl];
            v.x += bb; v.y += bb; v.z += bb; v.w += bb;
            *(float4*)&ob[(size_t)ocl * HW + pix] = v;
        }
    }
}

extern "C" void kernel_launch(void* const* d_in, const int* in_sizes, int n_in,
                              void* d_out, int out_size) {
    const float* x     = (const float*)d_in[0];
    const float* cw    = (const float*)d_in[1];
    const float* cb    = (const float*)d_in[2];
    const float* dw    = (const float*)d_in[3];
    const float* db    = (const float*)d_in[4];
    const float* fc1_w = (const float*)d_in[5];
    const float* fc2_w = (const float*)d_in[6];
    float* out = (float*)d_out;

    cudaFuncSetAttribute(conv_kernel, cudaFuncAttributeMaxDynamicSharedMemorySize, SM_TOT);

    convx_kernel<<<dim3(NPBLK, 2, BATCH), dim3(32, 8)>>>(x);
    mlp_kernel<<<BATCH, 128>>>(fc1_w, fc2_w);
    aggw_kernel<<<OUTC, 256>>>(cw, dw);
    conv_kernel<<<dim3(NPB, BATCH), 256, SM_TOT>>>(cb, db, out);
}

// round 12
// speedup vs baseline: 1.0141x; 1.0141x over previous
#include <cuda_runtime.h>
#include <cuda_fp16.h>
#include <cstdint>

#define BATCH 32
#define CIN 128
#define OUTC 128
#define HIDDEN 32
#define TEMP 31.0f
#define HW 3136
#define PIXB 128
#define NPB 25
#define NPBLK 98

// conv dynamic smem: bias @0, A halo (348 rows * 128B) @1024, B 2x16KB
#define SM_A 1024
#define A_ROWS 348
#define A_BYTES (A_ROWS * 128)       // 44544
#define SM_B (SM_A + A_BYTES)        // 45568
#define SM_TOT (SM_B + 2 * 16384)    // 78336

__device__ float g_attn[BATCH][2];
__device__ float g_part[BATCH * CIN * NPBLK];
__device__ __align__(16) __half g_xh[(size_t)BATCH * HW * CIN];          // NHWC
__device__ __align__(16) __half g_wagg[(size_t)BATCH * 9 * OUTC * CIN];  // [b][t][o][c]

#define SWZ(o) ((o) ^ (((o) >> 3) & 0x70))

__device__ __forceinline__ uint32_t smem_u32(const void* p) {
    uint32_t a;
    asm("{ .reg .u64 t; cvta.to.shared.u64 t, %1; cvt.u32.u64 %0, t; }" : "=r"(a) : "l"(p));
    return a;
}
__device__ __forceinline__ void ldm4(uint32_t* r, uint32_t addr) {
    asm volatile("ldmatrix.sync.aligned.m8n8.x4.shared.b16 {%0,%1,%2,%3}, [%4];"
                 : "=r"(r[0]), "=r"(r[1]), "=r"(r[2]), "=r"(r[3]) : "r"(addr));
}
__device__ __forceinline__ void mma16816(float* c, const uint32_t* a, const uint32_t* b) {
    asm volatile("mma.sync.aligned.m16n8k16.row.col.f32.f16.f16.f32 "
                 "{%0,%1,%2,%3}, {%4,%5,%6,%7}, {%8,%9}, {%0,%1,%2,%3};"
                 : "+f"(c[0]), "+f"(c[1]), "+f"(c[2]), "+f"(c[3])
                 : "r"(a[0]), "r"(a[1]), "r"(a[2]), "r"(a[3]), "r"(b[0]), "r"(b[1]));
}
__device__ __forceinline__ void cpasync16(uint32_t dst, const void* src, uint32_t srcsz) {
    asm volatile("cp.async.cg.shared.global [%0], [%1], 16, %2;"
                 :: "r"(dst), "l"(src), "r"(srcsz) : "memory");
}
#define CP_COMMIT() asm volatile("cp.async.commit_group;" ::: "memory")
#define CP_WAIT0()  asm volatile("cp.async.wait_group 0;" ::: "memory")

// ---- prolog 1: NCHW f32 -> NHWC fp16, 128c x 64px tiles, fused pooling ----
// grid (49, 1, BATCH), block 256. Coalesced float4 loads + full-row uint4 stores.
__global__ void __launch_bounds__(256)
convx_kernel(const float* __restrict__ x) {
    __shared__ float t[128][67];
    const int b = blockIdx.z, p0 = blockIdx.x * 64;
    const int tid = threadIdx.x;

    // load: 128 channels x 64 px, float4-coalesced (16 float4 per channel row)
    const float4* x4 = (const float4*)(x + (size_t)b * CIN * HW + p0);
    #pragma unroll
    for (int i = 0; i < 8; ++i) {
        int e = tid + i * 256;              // c*16 + j
        int c = e >> 4, j = e & 15;
        float4 v = x4[(size_t)c * (HW / 4) + j];
        t[c][j * 4 + 0] = v.x; t[c][j * 4 + 1] = v.y;
        t[c][j * 4 + 2] = v.z; t[c][j * 4 + 3] = v.w;
    }
    __syncthreads();

    // store: thread (p, q): pixel p, channel chunk q (32 channels = 4 uint4)
    {
        const int q = tid & 3, p = tid >> 2;
        uint32_t h2[16];
        #pragma unroll
        for (int j = 0; j < 16; ++j) {
            __half2 v = __floats2half2_rn(t[q * 32 + 2 * j][p], t[q * 32 + 2 * j + 1][p]);
            h2[j] = *(uint32_t*)&v;
        }
        uint4* dst = (uint4*)(g_xh + ((size_t)b * HW + p0 + p) * CIN + q * 32);
        dst[0] = make_uint4(h2[0],  h2[1],  h2[2],  h2[3]);
        dst[1] = make_uint4(h2[4],  h2[5],  h2[6],  h2[7]);
        dst[2] = make_uint4(h2[8],  h2[9],  h2[10], h2[11]);
        dst[3] = make_uint4(h2[12], h2[13], h2[14], h2[15]);
    }

    // pooling partials: thread (c, seg): sum 32 px
    {
        const int c = tid >> 1, seg = tid & 1;
        float s = 0.f;
        #pragma unroll
        for (int i = 0; i < 32; ++i) s += t[c][seg * 32 + i];
        g_part[((size_t)b * CIN + c) * NPBLK + blockIdx.x * 2 + seg] = s;
    }
}

// ---- prolog 2: reduce partials -> mlp -> softmax ----
__global__ void mlp_kernel(const float* __restrict__ fc1_w, const float* __restrict__ fc2_w) {
    const int b = blockIdx.x, tid = threadIdx.x;
    __shared__ float pooled[CIN], hid[HIDDEN], logits[2];
    if (tid < CIN) {
        const float* pp = g_part + (size_t)(b * CIN + tid) * NPBLK;
        float s = 0.f;
        for (int i = 0; i < NPBLK; ++i) s += pp[i];
        pooled[tid] = s * (1.0f / (float)HW);
    }
    __syncthreads();
    if (tid < HIDDEN) {
        float h = 0.f;
        for (int c = 0; c < CIN; ++c) h += pooled[c] * fc1_w[tid * CIN + c];
        hid[tid] = fmaxf(h, 0.f);
    }
    __syncthreads();
    if (tid < 2) {
        float l = 0.f;
        for (int j = 0; j < HIDDEN; ++j) l += hid[j] * fc2_w[tid * HIDDEN + j];
        logits[tid] = l;
    }
    __syncthreads();
    if (tid == 0) {
        float l0 = logits[0] / TEMP, l1 = logits[1] / TEMP;
        float m = fmaxf(l0, l1), e0 = __expf(l0 - m), e1 = __expf(l1 - m);
        float inv = 1.0f / (e0 + e1);
        g_attn[b][0] = e0 * inv;
        g_attn[b][1] = e1 * inv;
    }
}

// ---- prolog 3: weight aggregation -> fp16 [b][t][o][c], 512 CTAs ----
__global__ void aggw_kernel(const float* __restrict__ cw, const float* __restrict__ dw) {
    __shared__ float cs[1152], ds[1152];
    const int o = blockIdx.x, tid = threadIdx.x;
    for (int e = tid; e < 1152; e += 256) {
        cs[e] = cw[(size_t)o * 1152 + e];
        ds[e] = dw[(size_t)o * 1152 + e];
    }
    __syncthreads();
    const int c2 = tid & 63, q = tid >> 6;
    const int bt0 = blockIdx.y * 72 + q * 18;
    __half2* wg2 = (__half2*)g_wagg;
    for (int bt = bt0; bt < bt0 + 18; ++bt) {
        int b = bt / 9, t = bt - b * 9;
        float a0 = g_attn[b][0], a1 = g_attn[b][1];
        float v0 = a0 * cs[(2 * c2) * 9 + t] + a1 * ds[(2 * c2) * 9 + t];
        float v1 = a0 * cs[(2 * c2 + 1) * 9 + t] + a1 * ds[(2 * c2 + 1) * 9 + t];
        wg2[(((size_t)b * 9 + t) * OUTC + o) * 64 + c2] = __floats2half2_rn(v0, v1);
    }
}

// ---- main conv: HMMA implicit GEMM (R9 config: 18 single-tap stages) ----
__global__ void __launch_bounds__(256, 2)
conv_kernel(const float* __restrict__ cb, const float* __restrict__ db,
            float* __restrict__ out) {
    extern __shared__ char sm[];
    const uint32_t smb = smem_u32(sm);
    const int tid = threadIdx.x, wid = tid >> 5, lane = tid & 31;
    const int wm = wid & 3, wn = wid >> 2;
    const int b = blockIdx.y, pbase = blockIdx.x * PIXB;
    const int h0 = pbase / 56;

    float* bias = (float*)sm;
    if (tid < OUTC) bias[tid] = g_attn[b][0] * cb[tid] + g_attn[b][1] * db[tid];

    const __half* xb = g_xh + (size_t)b * HW * CIN;
    const __half* wb = g_wagg + (size_t)b * 9 * OUTC * CIN;

    int hh[2], ww[2];
    #pragma unroll
    for (int mi = 0; mi < 2; ++mi) {
        int p = pbase + wm * 32 + mi * 16 + (lane & 15);
        if (p >= HW) p = HW - 1;
        hh[mi] = p / 56;
        ww[mi] = p - hh[mi] * 56;
    }

    float acc[2][8][4];
    #pragma unroll
    for (int mi = 0; mi < 2; ++mi)
        #pragma unroll
        for (int ni = 0; ni < 8; ++ni)
            #pragma unroll
            for (int e = 0; e < 4; ++e) acc[mi][ni][e] = 0.f;

    uint32_t brow[4];
    #pragma unroll
    for (int nb = 0; nb < 4; ++nb)
        brow[nb] = (uint32_t)(wn * 64 + nb * 16 + (lane & 15)) * 128;
    const uint32_t bxr = (uint32_t)(lane & 7) << 4;
    const uint32_t ksub = (uint32_t)((lane >> 4) << 4);

    for (int e = tid; e < A_ROWS * 8; e += 256) {
        int rr = e >> 3, ch = e & 7;
        int ih = h0 - 1 + rr / 58, iw = rr % 58 - 1;
        bool ok = ((unsigned)ih < 56u) && ((unsigned)iw < 56u);
        const void* src = xb + (ok ? ((size_t)(ih * 56 + iw) * CIN + ch * 8) : 0);
        cpasync16(smb + SM_A + SWZ((uint32_t)rr * 128 + ch * 16), src, ok ? 16u : 0u);
    }
    #pragma unroll
    for (int i = 0; i < 4; ++i) {
        int e = tid + i * 256, o = e >> 3, ch = e & 7;
        cpasync16(smb + SM_B + SWZ((uint32_t)o * 128 + ch * 16),
                  wb + (size_t)o * CIN + ch * 8, 16u);
    }
    CP_COMMIT();
    CP_WAIT0();
    __syncthreads();

    for (int s = 0; s < 18; ++s) {
        const int hf = s / 9, t = s - hf * 9;
        if (s < 17) {
            const int sn = s + 1, hfn = sn / 9, tn = sn - hfn * 9;
            const __half* wsrc = wb + (size_t)tn * OUTC * CIN + hfn * 64;
            uint32_t buf = smb + SM_B + (uint32_t)((sn & 1) * 16384);
            #pragma unroll
            for (int i = 0; i < 4; ++i) {
                int e = tid + i * 256, o = e >> 3, ch = e & 7;
                cpasync16(buf + SWZ((uint32_t)o * 128 + ch * 16),
                          wsrc + (size_t)o * CIN + ch * 8, 16u);
            }
            CP_COMMIT();
        }

        const int di = t / 3, dj = t - di * 3;
        uint32_t abase[2], axr[2];
        #pragma unroll
        for (int mi = 0; mi < 2; ++mi) {
            uint32_t rr = (uint32_t)((hh[mi] - h0 + di) * 58 + ww[mi] + dj);
            abase[mi] = smb + SM_A + rr * 128;
            axr[mi] = (rr & 7) << 4;
        }
        const uint32_t bbuf = smb + SM_B + (uint32_t)((s & 1) * 16384);

        #pragma unroll
        for (int ks = 0; ks < 4; ++ks) {
            const uint32_t kb = (uint32_t)ks * 32 + ksub;
            uint32_t a[2][4], bf[8][2];
            #pragma unroll
            for (int mi = 0; mi < 2; ++mi)
                ldm4(a[mi], abase[mi] + (kb ^ axr[mi]));
            #pragma unroll
            for (int nb = 0; nb < 4; ++nb) {
                uint32_t r[4];
                ldm4(r, bbuf + brow[nb] + (kb ^ bxr));
                bf[nb * 2][0] = r[0]; bf[nb * 2][1] = r[2];
                bf[nb * 2 + 1][0] = r[1]; bf[nb * 2 + 1][1] = r[3];
            }
            #pragma unroll
            for (int mi = 0; mi < 2; ++mi)
                #pragma unroll
                for (int ni = 0; ni < 8; ++ni)
                    mma16816(acc[mi][ni], a[mi], bf[ni]);
        }

        if (s == 8) {
            __syncthreads();
            for (int e = tid; e < A_ROWS * 8; e += 256) {
                int rr = e >> 3, ch = e & 7;
                int ih = h0 - 1 + rr / 58, iw = rr % 58 - 1;
                bool ok = ((unsigned)ih < 56u) && ((unsigned)iw < 56u);
                const void* src = xb + (ok ? ((size_t)(ih * 56 + iw) * CIN + 64 + ch * 8) : 0);
                cpasync16(smb + SM_A + SWZ((uint32_t)rr * 128 + ch * 16), src, ok ? 16u : 0u);
            }
            CP_COMMIT();
        }
        if (s < 17) {
            CP_WAIT0();
            __syncthreads();
        }
    }

    // epilogue: stage C through smem (overlays A/B), coalesced float4 STG
    float* csm = (float*)(sm + SM_A);
    float* ob = out + (size_t)b * OUTC * HW;
    __syncthreads();
    #pragma unroll
    for (int mi = 0; mi < 2; ++mi) {
        const int prl = wm * 32 + mi * 16 + (lane >> 2);
        #pragma unroll
        for (int ni = 0; ni < 8; ++ni) {
            const int ocl = wn * 64 + ni * 8 + (lane & 3) * 2;
            csm[ocl * 132 + prl]           = acc[mi][ni][0];
            csm[(ocl + 1) * 132 + prl]     = acc[mi][ni][1];
            csm[ocl * 132 + prl + 8]       = acc[mi][ni][2];
            csm[(ocl + 1) * 132 + prl + 8] = acc[mi][ni][3];
        }
    }
    __syncthreads();
    #pragma unroll
    for (int i = 0; i < 16; ++i) {
        int idx = tid + i * 256;
        int ocl = idx >> 5, px4 = idx & 31;
        int pix = pbase + px4 * 4;
        if (pix < HW) {
            float4 v = *(float4*)&csm[ocl * 132 + px4 * 4];
            float bb = bias[ocl];
            v.x += bb; v.y += bb; v.z += bb; v.w += bb;
            *(float4*)&ob[(size_t)ocl * HW + pix] = v;
        }
    }
}

extern "C" void kernel_launch(void* const* d_in, const int* in_sizes, int n_in,
                              void* d_out, int out_size) {
    const float* x     = (const float*)d_in[0];
    const float* cw    = (const float*)d_in[1];
    const float* cb    = (const float*)d_in[2];
    const float* dw    = (const float*)d_in[3];
    const float* db    = (const float*)d_in[4];
    const float* fc1_w = (const float*)d_in[5];
    const float* fc2_w = (const float*)d_in[6];
    float* out = (float*)d_out;

    cudaFuncSetAttribute(conv_kernel, cudaFuncAttributeMaxDynamicSharedMemorySize, SM_TOT);

    convx_kernel<<<dim3(49, 1, BATCH), 256>>>(x);
    mlp_kernel<<<BATCH, 128>>>(fc1_w, fc2_w);
    aggw_kernel<<<dim3(OUTC, 4), 256>>>(cw, dw);
    conv_kernel<<<dim3(NPB, BATCH), 256, SM_TOT>>>(cb, db, out);
}

// round 13
// speedup vs baseline: 1.0559x; 1.0412x over previous
#include <cuda_runtime.h>
#include <cuda_fp16.h>
#include <cstdint>

#define BATCH 32
#define CIN 128
#define OUTC 128
#define HIDDEN 32
#define TEMP 31.0f
#define HW 3136
#define PIXB 128
#define NPB 25
#define NPBLK 98

// conv dynamic smem: bias @0, A halo (348 rows * 128B) @1024, B ring 4x16KB
#define SM_A 1024
#define A_ROWS 348
#define A_BYTES (A_ROWS * 128)       // 44544
#define SM_B (SM_A + A_BYTES)        // 45568
#define SM_TOT (SM_B + 4 * 16384)    // 111104 -> 2 CTAs/SM

__device__ float g_attn[BATCH][2];
__device__ float g_part[BATCH * CIN * NPBLK];
__device__ __align__(16) __half g_xh[(size_t)BATCH * HW * CIN];          // NHWC
__device__ __align__(16) __half g_wagg[(size_t)BATCH * 9 * OUTC * CIN];  // [b][t][o][c]

#define SWZ(o) ((o) ^ (((o) >> 3) & 0x70))

__device__ __forceinline__ uint32_t smem_u32(const void* p) {
    uint32_t a;
    asm("{ .reg .u64 t; cvta.to.shared.u64 t, %1; cvt.u32.u64 %0, t; }" : "=r"(a) : "l"(p));
    return a;
}
__device__ __forceinline__ void ldm4(uint32_t* r, uint32_t addr) {
    asm volatile("ldmatrix.sync.aligned.m8n8.x4.shared.b16 {%0,%1,%2,%3}, [%4];"
                 : "=r"(r[0]), "=r"(r[1]), "=r"(r[2]), "=r"(r[3]) : "r"(addr));
}
__device__ __forceinline__ void mma16816(float* c, const uint32_t* a, const uint32_t* b) {
    asm volatile("mma.sync.aligned.m16n8k16.row.col.f32.f16.f16.f32 "
                 "{%0,%1,%2,%3}, {%4,%5,%6,%7}, {%8,%9}, {%0,%1,%2,%3};"
                 : "+f"(c[0]), "+f"(c[1]), "+f"(c[2]), "+f"(c[3])
                 : "r"(a[0]), "r"(a[1]), "r"(a[2]), "r"(a[3]), "r"(b[0]), "r"(b[1]));
}
__device__ __forceinline__ void cpasync16(uint32_t dst, const void* src, uint32_t srcsz) {
    asm volatile("cp.async.cg.shared.global [%0], [%1], 16, %2;"
                 :: "r"(dst), "l"(src), "r"(srcsz) : "memory");
}
#define CP_COMMIT() asm volatile("cp.async.commit_group;" ::: "memory")
#define CP_WAIT0()  asm volatile("cp.async.wait_group 0;" ::: "memory")

// ---- prolog 1 (R9-proven): NCHW f32 -> NHWC fp16 + pooling partials ----
__global__ void convx_kernel(const float* __restrict__ x) {
    __shared__ float t[64][33];
    const int b = blockIdx.z, c0 = blockIdx.y * 64, p0 = blockIdx.x * 32;
    const int tx = threadIdx.x, ty = threadIdx.y;   // (32, 8)
    #pragma unroll
    for (int k = 0; k < 8; ++k)
        t[ty + 8 * k][tx] = x[((size_t)b * CIN + c0 + ty + 8 * k) * HW + p0 + tx];
    __syncthreads();
    __half2* xh2 = (__half2*)g_xh;
    #pragma unroll
    for (int kk = 0; kk < 4; ++kk) {
        int p = ty + 8 * kk;
        xh2[((size_t)b * HW + p0 + p) * 64 + (c0 >> 1) + tx] =
            __floats2half2_rn(t[2 * tx][p], t[2 * tx + 1][p]);
    }
    #pragma unroll
    for (int k = 0; k < 8; ++k) {
        int c = ty * 8 + k;
        float s = t[c][tx];
        #pragma unroll
        for (int o = 16; o; o >>= 1) s += __shfl_xor_sync(0xffffffffu, s, o);
        if (tx == 0) g_part[((size_t)b * CIN + c0 + c) * NPBLK + blockIdx.x] = s;
    }
}

// ---- prolog 2 (R9-proven): reduce partials -> mlp -> softmax ----
__global__ void mlp_kernel(const float* __restrict__ fc1_w, const float* __restrict__ fc2_w) {
    const int b = blockIdx.x, tid = threadIdx.x;
    __shared__ float pooled[CIN], hid[HIDDEN], logits[2];
    if (tid < CIN) {
        const float* pp = g_part + (size_t)(b * CIN + tid) * NPBLK;
        float s = 0.f;
        for (int i = 0; i < NPBLK; ++i) s += pp[i];
        pooled[tid] = s * (1.0f / (float)HW);
    }
    __syncthreads();
    if (tid < HIDDEN) {
        float h = 0.f;
        for (int c = 0; c < CIN; ++c) h += pooled[c] * fc1_w[tid * CIN + c];
        hid[tid] = fmaxf(h, 0.f);
    }
    __syncthreads();
    if (tid < 2) {
        float l = 0.f;
        for (int j = 0; j < HIDDEN; ++j) l += hid[j] * fc2_w[tid * HIDDEN + j];
        logits[tid] = l;
    }
    __syncthreads();
    if (tid == 0) {
        float l0 = logits[0] / TEMP, l1 = logits[1] / TEMP;
        float m = fmaxf(l0, l1), e0 = __expf(l0 - m), e1 = __expf(l1 - m);
        float inv = 1.0f / (e0 + e1);
        g_attn[b][0] = e0 * inv;
        g_attn[b][1] = e1 * inv;
    }
}

// ---- prolog 3 (R9-proven): weight aggregation -> fp16 [b][t][o][c] ----
__global__ void aggw_kernel(const float* __restrict__ cw, const float* __restrict__ dw) {
    __shared__ float cs[1152], ds[1152];
    const int o = blockIdx.x, tid = threadIdx.x;
    for (int e = tid; e < 1152; e += 256) {
        cs[e] = cw[(size_t)o * 1152 + e];
        ds[e] = dw[(size_t)o * 1152 + e];
    }
    __syncthreads();
    const int c2 = tid & 63, q = tid >> 6;
    __half2* wg2 = (__half2*)g_wagg;
    for (int bt = q * 72; bt < (q + 1) * 72; ++bt) {
        int b = bt / 9, t = bt - b * 9;
        float a0 = g_attn[b][0], a1 = g_attn[b][1];
        float v0 = a0 * cs[(2 * c2) * 9 + t] + a1 * ds[(2 * c2) * 9 + t];
        float v1 = a0 * cs[(2 * c2 + 1) * 9 + t] + a1 * ds[(2 * c2 + 1) * 9 + t];
        wg2[(((size_t)b * 9 + t) * OUTC + o) * 64 + c2] = __floats2half2_rn(v0, v1);
    }
}

// ---- main conv: HMMA implicit GEMM, 4-buffer B ring, barrier per 2 stages ----
__global__ void __launch_bounds__(256, 2)
conv_kernel(const float* __restrict__ cb, const float* __restrict__ db,
            float* __restrict__ out) {
    extern __shared__ char sm[];
    const uint32_t smb = smem_u32(sm);
    const int tid = threadIdx.x, wid = tid >> 5, lane = tid & 31;
    const int wm = wid & 3, wn = wid >> 2;
    const int b = blockIdx.y, pbase = blockIdx.x * PIXB;
    const int h0 = pbase / 56;

    float* bias = (float*)sm;
    if (tid < OUTC) bias[tid] = g_attn[b][0] * cb[tid] + g_attn[b][1] * db[tid];

    const __half* xb = g_xh + (size_t)b * HW * CIN;
    const __half* wb = g_wagg + (size_t)b * 9 * OUTC * CIN;

    int hh[2], ww[2];
    #pragma unroll
    for (int mi = 0; mi < 2; ++mi) {
        int p = pbase + wm * 32 + mi * 16 + (lane & 15);
        if (p >= HW) p = HW - 1;
        hh[mi] = p / 56;
        ww[mi] = p - hh[mi] * 56;
    }

    float acc[2][8][4];
    #pragma unroll
    for (int mi = 0; mi < 2; ++mi)
        #pragma unroll
        for (int ni = 0; ni < 8; ++ni)
            #pragma unroll
            for (int e = 0; e < 4; ++e) acc[mi][ni][e] = 0.f;

    uint32_t brow[4];
    #pragma unroll
    for (int nb = 0; nb < 4; ++nb)
        brow[nb] = (uint32_t)(wn * 64 + nb * 16 + (lane & 15)) * 128;
    const uint32_t bxr = (uint32_t)(lane & 7) << 4;
    const uint32_t ksub = (uint32_t)((lane >> 4) << 4);

    // hoisted B-staging addressing (per-thread, stage-invariant)
    uint32_t bdst[4];
    int boff[4];
    #pragma unroll
    for (int i = 0; i < 4; ++i) {
        int e = tid + i * 256, o = e >> 3, ch = e & 7;
        bdst[i] = SWZ((uint32_t)o * 128 + ch * 16);
        boff[i] = o * CIN + ch * 8;
    }

    // per-stage compute (verified R9 core)
    auto compute = [&](int s) {
        const int hf = s / 9, t = s - hf * 9;
        (void)hf;
        const int di = t / 3, dj = t - di * 3;
        uint32_t abase[2], axr[2];
        #pragma unroll
        for (int mi = 0; mi < 2; ++mi) {
            uint32_t rr = (uint32_t)((hh[mi] - h0 + di) * 58 + ww[mi] + dj);
            abase[mi] = smb + SM_A + rr * 128;
            axr[mi] = (rr & 7) << 4;
        }
        const uint32_t bbuf = smb + SM_B + (uint32_t)((s & 3) * 16384);
        #pragma unroll
        for (int ks = 0; ks < 4; ++ks) {
            const uint32_t kb = (uint32_t)ks * 32 + ksub;
            uint32_t a[2][4], bf[8][2];
            #pragma unroll
            for (int mi = 0; mi < 2; ++mi)
                ldm4(a[mi], abase[mi] + (kb ^ axr[mi]));
            #pragma unroll
            for (int nb = 0; nb < 4; ++nb) {
                uint32_t r[4];
                ldm4(r, bbuf + brow[nb] + (kb ^ bxr));
                bf[nb * 2][0] = r[0]; bf[nb * 2][1] = r[2];
                bf[nb * 2 + 1][0] = r[1]; bf[nb * 2 + 1][1] = r[3];
            }
            #pragma unroll
            for (int mi = 0; mi < 2; ++mi)
                #pragma unroll
                for (int ni = 0; ni < 8; ++ni)
                    mma16816(acc[mi][ni], a[mi], bf[ni]);
        }
    };

    // initial staging: A half 0 + B stages 0,1
    for (int e = tid; e < A_ROWS * 8; e += 256) {
        int rr = e >> 3, ch = e & 7;
        int ih = h0 - 1 + rr / 58, iw = rr % 58 - 1;
        bool ok = ((unsigned)ih < 56u) && ((unsigned)iw < 56u);
        const void* src = xb + (ok ? ((size_t)(ih * 56 + iw) * CIN + ch * 8) : 0);
        cpasync16(smb + SM_A + SWZ((uint32_t)rr * 128 + ch * 16), src, ok ? 16u : 0u);
    }
    #pragma unroll
    for (int j = 0; j < 2; ++j) {
        const __half* src = wb + (size_t)j * OUTC * CIN;   // stages 0,1: hf=0,t=j
        uint32_t buf = smb + SM_B + (uint32_t)(j * 16384);
        #pragma unroll
        for (int i = 0; i < 4; ++i)
            cpasync16(buf + bdst[i], src + boff[i], 16u);
    }
    CP_COMMIT();
    CP_WAIT0();
    __syncthreads();

    // 9 pairs of stages
    for (int p = 0; p < 9; ++p) {
        if (p < 8) {
            #pragma unroll
            for (int j = 0; j < 2; ++j) {
                const int sn = 2 * p + 2 + j;
                const int hfn = sn / 9, tn = sn - hfn * 9;
                const __half* src = wb + (size_t)tn * OUTC * CIN + hfn * 64;
                uint32_t buf = smb + SM_B + (uint32_t)((sn & 3) * 16384);
                #pragma unroll
                for (int i = 0; i < 4; ++i)
                    cpasync16(buf + bdst[i], src + boff[i], 16u);
            }
            CP_COMMIT();
        }

        compute(2 * p);

        if (p == 4) {
            // half boundary: restage A for channels 64..127 (stage 9+ reads)
            __syncthreads();
            for (int e = tid; e < A_ROWS * 8; e += 256) {
                int rr = e >> 3, ch = e & 7;
                int ih = h0 - 1 + rr / 58, iw = rr % 58 - 1;
                bool ok = ((unsigned)ih < 56u) && ((unsigned)iw < 56u);
                const void* src = xb + (ok ? ((size_t)(ih * 56 + iw) * CIN + 64 + ch * 8) : 0);
                cpasync16(smb + SM_A + SWZ((uint32_t)rr * 128 + ch * 16), src, ok ? 16u : 0u);
            }
            CP_COMMIT();
            CP_WAIT0();
            __syncthreads();
        }

        compute(2 * p + 1);

        if (p < 8) {
            CP_WAIT0();
            __syncthreads();
        }
    }

    // epilogue: stage C through smem (overlays A/B), coalesced float4 STG
    float* csm = (float*)(sm + SM_A);
    float* ob = out + (size_t)b * OUTC * HW;
    __syncthreads();
    #pragma unroll
    for (int mi = 0; mi < 2; ++mi) {
        const int prl = wm * 32 + mi * 16 + (lane >> 2);
        #pragma unroll
        for (int ni = 0; ni < 8; ++ni) {
            const int ocl = wn * 64 + ni * 8 + (lane & 3) * 2;
            csm[ocl * 132 + prl]           = acc[mi][ni][0];
            csm[(ocl + 1) * 132 + prl]     = acc[mi][ni][1];
            csm[ocl * 132 + prl + 8]       = acc[mi][ni][2];
            csm[(ocl + 1) * 132 + prl + 8] = acc[mi][ni][3];
        }
    }
    __syncthreads();
    #pragma unroll
    for (int i = 0; i < 16; ++i) {
        int idx = tid + i * 256;
        int ocl = idx >> 5, px4 = idx & 31;
        int pix = pbase + px4 * 4;
        if (pix < HW) {
            float4 v = *(float4*)&csm[ocl * 132 + px4 * 4];
            float bb = bias[ocl];
            v.x += bb; v.y += bb; v.z += bb; v.w += bb;
            *(float4*)&ob[(size_t)ocl * HW + pix] = v;
        }
    }
}

extern "C" void kernel_launch(void* const* d_in, const int* in_sizes, int n_in,
                              void* d_out, int out_size) {
    const float* x     = (const float*)d_in[0];
    const float* cw    = (const float*)d_in[1];
    const float* cb    = (const float*)d_in[2];
    const float* dw    = (const float*)d_in[3];
    const float* db    = (const float*)d_in[4];
    const float* fc1_w = (const float*)d_in[5];
    const float* fc2_w = (const float*)d_in[6];
    float* out = (float*)d_out;

    cudaFuncSetAttribute(conv_kernel, cudaFuncAttributeMaxDynamicSharedMemorySize, SM_TOT);

    convx_kernel<<<dim3(NPBLK, 2, BATCH), dim3(32, 8)>>>(x);
    mlp_kernel<<<BATCH, 128>>>(fc1_w, fc2_w);
    aggw_kernel<<<OUTC, 256>>>(cw, dw);
    conv_kernel<<<dim3(NPB, BATCH), 256, SM_TOT>>>(cb, db, out);
}

// round 14
// speedup vs baseline: 1.1079x; 1.0493x over previous
#include <cuda_runtime.h>
#include <cuda_fp16.h>
#include <cstdint>

#define BATCH 32
#define CIN 128
#define OUTC 128
#define HIDDEN 32
#define TEMP 31.0f
#define HW 3136
#define PIXB 128
#define NPB 25
#define NPBLK 98

// conv dynamic smem: bias @0, A halo (348 rows * 128B) @1024, B ring 4x16KB
#define SM_A 1024
#define A_ROWS 348
#define A_BYTES (A_ROWS * 128)       // 44544
#define SM_B (SM_A + A_BYTES)        // 45568
#define SM_TOT (SM_B + 4 * 16384)    // 111104 -> 2 CTAs/SM

__device__ float g_attn[BATCH][2];
__device__ float g_part[BATCH * CIN * NPBLK];
__device__ __align__(16) __half g_xh[(size_t)BATCH * HW * CIN];          // NHWC
__device__ __align__(16) __half g_wagg[(size_t)BATCH * 9 * OUTC * CIN];  // [b][t][o][c]

#define SWZ(o) ((o) ^ (((o) >> 3) & 0x70))

__device__ __forceinline__ uint32_t smem_u32(const void* p) {
    uint32_t a;
    asm("{ .reg .u64 t; cvta.to.shared.u64 t, %1; cvt.u32.u64 %0, t; }" : "=r"(a) : "l"(p));
    return a;
}
__device__ __forceinline__ void ldm4(uint32_t* r, uint32_t addr) {
    asm volatile("ldmatrix.sync.aligned.m8n8.x4.shared.b16 {%0,%1,%2,%3}, [%4];"
                 : "=r"(r[0]), "=r"(r[1]), "=r"(r[2]), "=r"(r[3]) : "r"(addr));
}
__device__ __forceinline__ void mma16816(float* c, const uint32_t* a, const uint32_t* b) {
    asm volatile("mma.sync.aligned.m16n8k16.row.col.f32.f16.f16.f32 "
                 "{%0,%1,%2,%3}, {%4,%5,%6,%7}, {%8,%9}, {%0,%1,%2,%3};"
                 : "+f"(c[0]), "+f"(c[1]), "+f"(c[2]), "+f"(c[3])
                 : "r"(a[0]), "r"(a[1]), "r"(a[2]), "r"(a[3]), "r"(b[0]), "r"(b[1]));
}
__device__ __forceinline__ void cpasync16(uint32_t dst, const void* src, uint32_t srcsz) {
    asm volatile("cp.async.cg.shared.global [%0], [%1], 16, %2;"
                 :: "r"(dst), "l"(src), "r"(srcsz) : "memory");
}
#define CP_COMMIT() asm volatile("cp.async.commit_group;" ::: "memory")
#define CP_WAIT0()  asm volatile("cp.async.wait_group 0;" ::: "memory")

// ---- prolog 1: NCHW f32 -> NHWC fp16; float4 loads + register pooling ----
// grid (98, 2, 32), block 256. 64 channels x 32 px per CTA.
__global__ void __launch_bounds__(256)
convx_kernel(const float* __restrict__ x) {
    __shared__ float t[64][33];
    const int b = blockIdx.z, c0 = blockIdx.y * 64, p0 = blockIdx.x * 32;
    const int tid = threadIdx.x;

    // load 64 rows x 8 float4 (2 per thread); pool each row in registers
    #pragma unroll
    for (int i = 0; i < 2; ++i) {
        int e = tid + i * 256;
        int row = e >> 3, j = e & 7;
        float4 v = *(const float4*)(x + ((size_t)b * CIN + c0 + row) * HW + p0 + 4 * j);
        t[row][4 * j + 0] = v.x; t[row][4 * j + 1] = v.y;
        t[row][4 * j + 2] = v.z; t[row][4 * j + 3] = v.w;
        float ps = v.x + v.y + v.z + v.w;
        ps += __shfl_xor_sync(0xffffffffu, ps, 1);
        ps += __shfl_xor_sync(0xffffffffu, ps, 2);
        ps += __shfl_xor_sync(0xffffffffu, ps, 4);
        if ((tid & 7) == 0)
            g_part[((size_t)b * CIN + c0 + row) * NPBLK + blockIdx.x] = ps;
    }
    __syncthreads();

    // store NHWC half2 (proven R9 pattern)
    const int tx = tid & 31, tyy = tid >> 5;
    __half2* xh2 = (__half2*)g_xh;
    #pragma unroll
    for (int kk = 0; kk < 4; ++kk) {
        int p = tyy + 8 * kk;
        xh2[((size_t)b * HW + p0 + p) * 64 + (c0 >> 1) + tx] =
            __floats2half2_rn(t[2 * tx][p], t[2 * tx + 1][p]);
    }
}

// ---- prolog 2 (R9-proven): reduce partials -> mlp -> softmax ----
__global__ void mlp_kernel(const float* __restrict__ fc1_w, const float* __restrict__ fc2_w) {
    const int b = blockIdx.x, tid = threadIdx.x;
    __shared__ float pooled[CIN], hid[HIDDEN], logits[2];
    if (tid < CIN) {
        const float* pp = g_part + (size_t)(b * CIN + tid) * NPBLK;
        float s = 0.f;
        for (int i = 0; i < NPBLK; ++i) s += pp[i];
        pooled[tid] = s * (1.0f / (float)HW);
    }
    __syncthreads();
    if (tid < HIDDEN) {
        float h = 0.f;
        for (int c = 0; c < CIN; ++c) h += pooled[c] * fc1_w[tid * CIN + c];
        hid[tid] = fmaxf(h, 0.f);
    }
    __syncthreads();
    if (tid < 2) {
        float l = 0.f;
        for (int j = 0; j < HIDDEN; ++j) l += hid[j] * fc2_w[tid * HIDDEN + j];
        logits[tid] = l;
    }
    __syncthreads();
    if (tid == 0) {
        float l0 = logits[0] / TEMP, l1 = logits[1] / TEMP;
        float m = fmaxf(l0, l1), e0 = __expf(l0 - m), e1 = __expf(l1 - m);
        float inv = 1.0f / (e0 + e1);
        g_attn[b][0] = e0 * inv;
        g_attn[b][1] = e1 * inv;
    }
}

// ---- prolog 3 (R9-proven): weight aggregation -> fp16 [b][t][o][c] ----
__global__ void aggw_kernel(const float* __restrict__ cw, const float* __restrict__ dw) {
    __shared__ float cs[1152], ds[1152];
    const int o = blockIdx.x, tid = threadIdx.x;
    for (int e = tid; e < 1152; e += 256) {
        cs[e] = cw[(size_t)o * 1152 + e];
        ds[e] = dw[(size_t)o * 1152 + e];
    }
    __syncthreads();
    const int c2 = tid & 63, q = tid >> 6;
    __half2* wg2 = (__half2*)g_wagg;
    for (int bt = q * 72; bt < (q + 1) * 72; ++bt) {
        int b = bt / 9, t = bt - b * 9;
        float a0 = g_attn[b][0], a1 = g_attn[b][1];
        float v0 = a0 * cs[(2 * c2) * 9 + t] + a1 * ds[(2 * c2) * 9 + t];
        float v1 = a0 * cs[(2 * c2 + 1) * 9 + t] + a1 * ds[(2 * c2 + 1) * 9 + t];
        wg2[(((size_t)b * 9 + t) * OUTC + o) * 64 + c2] = __floats2half2_rn(v0, v1);
    }
}

// ---- main conv (R13-proven): HMMA implicit GEMM, 4-buffer B ring ----
__global__ void __launch_bounds__(256, 2)
conv_kernel(const float* __restrict__ cb, const float* __restrict__ db,
            float* __restrict__ out) {
    extern __shared__ char sm[];
    const uint32_t smb = smem_u32(sm);
    const int tid = threadIdx.x, wid = tid >> 5, lane = tid & 31;
    const int wm = wid & 3, wn = wid >> 2;
    const int b = blockIdx.y, pbase = blockIdx.x * PIXB;
    const int h0 = pbase / 56;

    float* bias = (float*)sm;
    if (tid < OUTC) bias[tid] = g_attn[b][0] * cb[tid] + g_attn[b][1] * db[tid];

    const __half* xb = g_xh + (size_t)b * HW * CIN;
    const __half* wb = g_wagg + (size_t)b * 9 * OUTC * CIN;

    int hh[2], ww[2];
    #pragma unroll
    for (int mi = 0; mi < 2; ++mi) {
        int p = pbase + wm * 32 + mi * 16 + (lane & 15);
        if (p >= HW) p = HW - 1;
        hh[mi] = p / 56;
        ww[mi] = p - hh[mi] * 56;
    }

    float acc[2][8][4];
    #pragma unroll
    for (int mi = 0; mi < 2; ++mi)
        #pragma unroll
        for (int ni = 0; ni < 8; ++ni)
            #pragma unroll
            for (int e = 0; e < 4; ++e) acc[mi][ni][e] = 0.f;

    uint32_t brow[4];
    #pragma unroll
    for (int nb = 0; nb < 4; ++nb)
        brow[nb] = (uint32_t)(wn * 64 + nb * 16 + (lane & 15)) * 128;
    const uint32_t bxr = (uint32_t)(lane & 7) << 4;
    const uint32_t ksub = (uint32_t)((lane >> 4) << 4);

    uint32_t bdst[4];
    int boff[4];
    #pragma unroll
    for (int i = 0; i < 4; ++i) {
        int e = tid + i * 256, o = e >> 3, ch = e & 7;
        bdst[i] = SWZ((uint32_t)o * 128 + ch * 16);
        boff[i] = o * CIN + ch * 8;
    }

    auto compute = [&](int s) {
        const int hf = s / 9, t = s - hf * 9;
        (void)hf;
        const int di = t / 3, dj = t - di * 3;
        uint32_t abase[2], axr[2];
        #pragma unroll
        for (int mi = 0; mi < 2; ++mi) {
            uint32_t rr = (uint32_t)((hh[mi] - h0 + di) * 58 + ww[mi] + dj);
            abase[mi] = smb + SM_A + rr * 128;
            axr[mi] = (rr & 7) << 4;
        }
        const uint32_t bbuf = smb + SM_B + (uint32_t)((s & 3) * 16384);
        #pragma unroll
        for (int ks = 0; ks < 4; ++ks) {
            const uint32_t kb = (uint32_t)ks * 32 + ksub;
            uint32_t a[2][4], bf[8][2];
            #pragma unroll
            for (int mi = 0; mi < 2; ++mi)
                ldm4(a[mi], abase[mi] + (kb ^ axr[mi]));
            #pragma unroll
            for (int nb = 0; nb < 4; ++nb) {
                uint32_t r[4];
                ldm4(r, bbuf + brow[nb] + (kb ^ bxr));
                bf[nb * 2][0] = r[0]; bf[nb * 2][1] = r[2];
                bf[nb * 2 + 1][0] = r[1]; bf[nb * 2 + 1][1] = r[3];
            }
            #pragma unroll
            for (int mi = 0; mi < 2; ++mi)
                #pragma unroll
                for (int ni = 0; ni < 8; ++ni)
                    mma16816(acc[mi][ni], a[mi], bf[ni]);
        }
    };

    for (int e = tid; e < A_ROWS * 8; e += 256) {
        int rr = e >> 3, ch = e & 7;
        int ih = h0 - 1 + rr / 58, iw = rr % 58 - 1;
        bool ok = ((unsigned)ih < 56u) && ((unsigned)iw < 56u);
        const void* src = xb + (ok ? ((size_t)(ih * 56 + iw) * CIN + ch * 8) : 0);
        cpasync16(smb + SM_A + SWZ((uint32_t)rr * 128 + ch * 16), src, ok ? 16u : 0u);
    }
    #pragma unroll
    for (int j = 0; j < 2; ++j) {
        const __half* src = wb + (size_t)j * OUTC * CIN;
        uint32_t buf = smb + SM_B + (uint32_t)(j * 16384);
        #pragma unroll
        for (int i = 0; i < 4; ++i)
            cpasync16(buf + bdst[i], src + boff[i], 16u);
    }
    CP_COMMIT();
    CP_WAIT0();
    __syncthreads();

    for (int p = 0; p < 9; ++p) {
        if (p < 8) {
            #pragma unroll
            for (int j = 0; j < 2; ++j) {
                const int sn = 2 * p + 2 + j;
                const int hfn = sn / 9, tn = sn - hfn * 9;
                const __half* src = wb + (size_t)tn * OUTC * CIN + hfn * 64;
                uint32_t buf = smb + SM_B + (uint32_t)((sn & 3) * 16384);
                #pragma unroll
                for (int i = 0; i < 4; ++i)
                    cpasync16(buf + bdst[i], src + boff[i], 16u);
            }
            CP_COMMIT();
        }

        compute(2 * p);

        if (p == 4) {
            __syncthreads();
            for (int e = tid; e < A_ROWS * 8; e += 256) {
                int rr = e >> 3, ch = e & 7;
                int ih = h0 - 1 + rr / 58, iw = rr % 58 - 1;
                bool ok = ((unsigned)ih < 56u) && ((unsigned)iw < 56u);
                const void* src = xb + (ok ? ((size_t)(ih * 56 + iw) * CIN + 64 + ch * 8) : 0);
                cpasync16(smb + SM_A + SWZ((uint32_t)rr * 128 + ch * 16), src, ok ? 16u : 0u);
            }
            CP_COMMIT();
            CP_WAIT0();
            __syncthreads();
        }

        compute(2 * p + 1);

        if (p < 8) {
            CP_WAIT0();
            __syncthreads();
        }
    }

    float* csm = (float*)(sm + SM_A);
    float* ob = out + (size_t)b * OUTC * HW;
    __syncthreads();
    #pragma unroll
    for (int mi = 0; mi < 2; ++mi) {
        const int prl = wm * 32 + mi * 16 + (lane >> 2);
        #pragma unroll
        for (int ni = 0; ni < 8; ++ni) {
            const int ocl = wn * 64 + ni * 8 + (lane & 3) * 2;
            csm[ocl * 132 + prl]           = acc[mi][ni][0];
            csm[(ocl + 1) * 132 + prl]     = acc[mi][ni][1];
            csm[ocl * 132 + prl + 8]       = acc[mi][ni][2];
            csm[(ocl + 1) * 132 + prl + 8] = acc[mi][ni][3];
        }
    }
    __syncthreads();
    #pragma unroll
    for (int i = 0; i < 16; ++i) {
        int idx = tid + i * 256;
        int ocl = idx >> 5, px4 = idx & 31;
        int pix = pbase + px4 * 4;
        if (pix < HW) {
            float4 v = *(float4*)&csm[ocl * 132 + px4 * 4];
            float bb = bias[ocl];
            v.x += bb; v.y += bb; v.z += bb; v.w += bb;
            *(float4*)&ob[(size_t)ocl * HW + pix] = v;
        }
    }
}

extern "C" void kernel_launch(void* const* d_in, const int* in_sizes, int n_in,
                              void* d_out, int out_size) {
    const float* x     = (const float*)d_in[0];
    const float* cw    = (const float*)d_in[1];
    const float* cb    = (const float*)d_in[2];
    const float* dw    = (const float*)d_in[3];
    const float* db    = (const float*)d_in[4];
    const float* fc1_w = (const float*)d_in[5];
    const float* fc2_w = (const float*)d_in[6];
    float* out = (float*)d_out;

    cudaFuncSetAttribute(conv_kernel, cudaFuncAttributeMaxDynamicSharedMemorySize, SM_TOT);

    convx_kernel<<<dim3(NPBLK, 2, BATCH), 256>>>(x);
    mlp_kernel<<<BATCH, 128>>>(fc1_w, fc2_w);
    aggw_kernel<<<OUTC, 256>>>(cw, dw);
    conv_kernel<<<dim3(NPB, BATCH), 256, SM_TOT>>>(cb, db, out);
}

// round 16
// speedup vs baseline: 1.1368x; 1.0261x over previous
#include <cuda_runtime.h>
#include <cuda_fp16.h>
#include <cstdint>

#define BATCH 32
#define CIN 128
#define OUTC 128
#define HIDDEN 32
#define TEMP 31.0f
#define HW 3136
#define PIXB 128
#define NPB 25
#define NPBLK 49

// conv dynamic smem: bias @0, A halo (348 rows * 128B) @1024, B ring 4x16KB
#define SM_A 1024
#define A_ROWS 348
#define A_BYTES (A_ROWS * 128)       // 44544
#define SM_B (SM_A + A_BYTES)        // 45568
#define SM_TOT (SM_B + 4 * 16384)    // 111104 -> 2 CTAs/SM

__device__ float g_attn[BATCH][2];
__device__ float g_part[BATCH * NPBLK * CIN];   // [b][blk][c] (coalesced reduce)
__device__ __align__(16) __half g_xh[(size_t)BATCH * HW * CIN];          // NHWC
__device__ __align__(16) __half g_wagg[(size_t)BATCH * 9 * OUTC * CIN];  // [b][t][o][c]

#define SWZ(o) ((o) ^ (((o) >> 3) & 0x70))

__device__ __forceinline__ uint32_t smem_u32(const void* p) {
    uint32_t a;
    asm("{ .reg .u64 t; cvta.to.shared.u64 t, %1; cvt.u32.u64 %0, t; }" : "=r"(a) : "l"(p));
    return a;
}
__device__ __forceinline__ void ldm4(uint32_t* r, uint32_t addr) {
    asm volatile("ldmatrix.sync.aligned.m8n8.x4.shared.b16 {%0,%1,%2,%3}, [%4];"
                 : "=r"(r[0]), "=r"(r[1]), "=r"(r[2]), "=r"(r[3]) : "r"(addr));
}
__device__ __forceinline__ void mma16816(float* c, const uint32_t* a, const uint32_t* b) {
    asm volatile("mma.sync.aligned.m16n8k16.row.col.f32.f16.f16.f32 "
                 "{%0,%1,%2,%3}, {%4,%5,%6,%7}, {%8,%9}, {%0,%1,%2,%3};"
                 : "+f"(c[0]), "+f"(c[1]), "+f"(c[2]), "+f"(c[3])
                 : "r"(a[0]), "r"(a[1]), "r"(a[2]), "r"(a[3]), "r"(b[0]), "r"(b[1]));
}
__device__ __forceinline__ void cpasync16(uint32_t dst, const void* src, uint32_t srcsz) {
    asm volatile("cp.async.cg.shared.global [%0], [%1], 16, %2;"
                 :: "r"(dst), "l"(src), "r"(srcsz) : "memory");
}
#define CP_COMMIT() asm volatile("cp.async.commit_group;" ::: "memory")
#define CP_WAIT0()  asm volatile("cp.async.wait_group 0;" ::: "memory")

// ---- prolog 1: NCHW f32 -> NHWC fp16; 64ch x 64px tiles, register pooling ----
// grid (49, 2, 32), block 256.
__global__ void __launch_bounds__(256)
convx_kernel(const float* __restrict__ x) {
    __shared__ float t[64][65];
    const int b = blockIdx.z, c0 = blockIdx.y * 64, p0 = blockIdx.x * 64;
    const int tid = threadIdx.x;

    // load 64 rows x 16 float4 (4 per thread); pool each row in registers
    #pragma unroll
    for (int i = 0; i < 4; ++i) {
        int e = tid + i * 256;
        int row = e >> 4, j = e & 15;
        float4 v = *(const float4*)(x + ((size_t)b * CIN + c0 + row) * HW + p0 + 4 * j);
        t[row][4 * j + 0] = v.x; t[row][4 * j + 1] = v.y;
        t[row][4 * j + 2] = v.z; t[row][4 * j + 3] = v.w;
        float ps = v.x + v.y + v.z + v.w;
        #pragma unroll
        for (int o = 1; o < 16; o <<= 1) ps += __shfl_xor_sync(0xffffffffu, ps, o);
        if ((tid & 15) == 0)
            g_part[((size_t)b * NPBLK + blockIdx.x) * CIN + c0 + row] = ps;
    }
    __syncthreads();

    // store NHWC half2: two 32-px groups, proven pattern
    const int tx = tid & 31, tyy = tid >> 5;
    __half2* xh2 = (__half2*)g_xh;
    #pragma unroll
    for (int g = 0; g < 2; ++g) {
        #pragma unroll
        for (int kk = 0; kk < 4; ++kk) {
            int p = g * 32 + tyy + 8 * kk;
            xh2[((size_t)b * HW + p0 + p) * 64 + (c0 >> 1) + tx] =
                __floats2half2_rn(t[2 * tx][p], t[2 * tx + 1][p]);
        }
    }
}

// ---- prolog 2: reduce partials (coalesced) -> mlp -> softmax ----
__global__ void mlp_kernel(const float* __restrict__ fc1_w, const float* __restrict__ fc2_w) {
    const int b = blockIdx.x, tid = threadIdx.x;
    __shared__ float pooled[CIN], hid[HIDDEN], logits[2];
    if (tid < CIN) {
        const float* pp = g_part + (size_t)b * NPBLK * CIN + tid;
        float s = 0.f;
        #pragma unroll 7
        for (int i = 0; i < NPBLK; ++i) s += pp[i * CIN];
        pooled[tid] = s * (1.0f / (float)HW);
    }
    __syncthreads();
    if (tid < HIDDEN) {
        float h = 0.f;
        for (int c = 0; c < CIN; ++c) h += pooled[c] * fc1_w[tid * CIN + c];
        hid[tid] = fmaxf(h, 0.f);
    }
    __syncthreads();
    if (tid < 2) {
        float l = 0.f;
        for (int j = 0; j < HIDDEN; ++j) l += hid[j] * fc2_w[tid * HIDDEN + j];
        logits[tid] = l;
    }
    __syncthreads();
    if (tid == 0) {
        float l0 = logits[0] / TEMP, l1 = logits[1] / TEMP;
        float m = fmaxf(l0, l1), e0 = __expf(l0 - m), e1 = __expf(l1 - m);
        float inv = 1.0f / (e0 + e1);
        g_attn[b][0] = e0 * inv;
        g_attn[b][1] = e1 * inv;
    }
}

// ---- prolog 3 (R9-proven): weight aggregation -> fp16 [b][t][o][c] ----
__global__ void aggw_kernel(const float* __restrict__ cw, const float* __restrict__ dw) {
    __shared__ float cs[1152], ds[1152];
    const int o = blockIdx.x, tid = threadIdx.x;
    for (int e = tid; e < 1152; e += 256) {
        cs[e] = cw[(size_t)o * 1152 + e];
        ds[e] = dw[(size_t)o * 1152 + e];
    }
    __syncthreads();
    const int c2 = tid & 63, q = tid >> 6;
    __half2* wg2 = (__half2*)g_wagg;
    for (int bt = q * 72; bt < (q + 1) * 72; ++bt) {
        int b = bt / 9, t = bt - b * 9;
        float a0 = g_attn[b][0], a1 = g_attn[b][1];
        float v0 = a0 * cs[(2 * c2) * 9 + t] + a1 * ds[(2 * c2) * 9 + t];
        float v1 = a0 * cs[(2 * c2 + 1) * 9 + t] + a1 * ds[(2 * c2 + 1) * 9 + t];
        wg2[(((size_t)b * 9 + t) * OUTC + o) * 64 + c2] = __floats2half2_rn(v0, v1);
    }
}

// ---- main conv (R13 core): HMMA implicit GEMM, 4-buffer B ring ----
__global__ void __launch_bounds__(256, 2)
conv_kernel(const float* __restrict__ cb, const float* __restrict__ db,
            float* __restrict__ out) {
    extern __shared__ char sm[];
    const uint32_t smb = smem_u32(sm);
    const int tid = threadIdx.x, wid = tid >> 5, lane = tid & 31;
    const int wm = wid & 3, wn = wid >> 2;
    const int b = blockIdx.y, pbase = blockIdx.x * PIXB;
    const int h0 = pbase / 56;

    float* bias = (float*)sm;
    if (tid < OUTC) bias[tid] = g_attn[b][0] * cb[tid] + g_attn[b][1] * db[tid];

    const __half* xb = g_xh + (size_t)b * HW * CIN;
    const __half* wb = g_wagg + (size_t)b * 9 * OUTC * CIN;

    int hh[2], ww[2];
    #pragma unroll
    for (int mi = 0; mi < 2; ++mi) {
        int p = pbase + wm * 32 + mi * 16 + (lane & 15);
        if (p >= HW) p = HW - 1;
        hh[mi] = p / 56;
        ww[mi] = p - hh[mi] * 56;
    }

    float acc[2][8][4];
    #pragma unroll
    for (int mi = 0; mi < 2; ++mi)
        #pragma unroll
        for (int ni = 0; ni < 8; ++ni)
            #pragma unroll
            for (int e = 0; e < 4; ++e) acc[mi][ni][e] = 0.f;

    uint32_t brow[4];
    #pragma unroll
    for (int nb = 0; nb < 4; ++nb)
        brow[nb] = (uint32_t)(wn * 64 + nb * 16 + (lane & 15)) * 128;
    const uint32_t bxr = (uint32_t)(lane & 7) << 4;
    const uint32_t ksub = (uint32_t)((lane >> 4) << 4);

    uint32_t bdst[4];
    int boff[4];
    #pragma unroll
    for (int i = 0; i < 4; ++i) {
        int e = tid + i * 256, o = e >> 3, ch = e & 7;
        bdst[i] = SWZ((uint32_t)o * 128 + ch * 16);
        boff[i] = o * CIN + ch * 8;
    }

    // division-free A halo staging; swizzle applied to FULL offset (rr*128+ch*16)
    auto stageA = [&](int cofs) {
        #pragma unroll
        for (int ir = 0; ir < 6; ++ir) {
            const int ih = h0 - 1 + ir;
            const bool rok = ((unsigned)ih < 56u);
            #pragma unroll
            for (int i = 0; i < 2; ++i) {
                int e = tid + i * 256;          // 464 elems: col*8 + ch
                if (e < 464) {
                    int col = e >> 3, ch = e & 7;
                    int rr = ir * 58 + col;
                    bool ok = rok && col >= 1 && col <= 56;
                    const void* src = xb + (ok ? ((size_t)(ih * 56 + col - 1) * CIN + cofs + ch * 8) : 0);
                    cpasync16(smb + SM_A + SWZ((uint32_t)rr * 128 + ch * 16), src, ok ? 16u : 0u);
                }
            }
        }
    };

    auto compute = [&](int s) {
        const int hf = s / 9, t = s - hf * 9;
        (void)hf;
        const int di = t / 3, dj = t - di * 3;
        uint32_t abase[2], axr[2];
        #pragma unroll
        for (int mi = 0; mi < 2; ++mi) {
            uint32_t rr = (uint32_t)((hh[mi] - h0 + di) * 58 + ww[mi] + dj);
            abase[mi] = smb + SM_A + rr * 128;
            axr[mi] = (rr & 7) << 4;
        }
        const uint32_t bbuf = smb + SM_B + (uint32_t)((s & 3) * 16384);
        #pragma unroll
        for (int ks = 0; ks < 4; ++ks) {
            const uint32_t kb = (uint32_t)ks * 32 + ksub;
            uint32_t a[2][4], bf[8][2];
            #pragma unroll
            for (int mi = 0; mi < 2; ++mi)
                ldm4(a[mi], abase[mi] + (kb ^ axr[mi]));
            #pragma unroll
            for (int nb = 0; nb < 4; ++nb) {
                uint32_t r[4];
                ldm4(r, bbuf + brow[nb] + (kb ^ bxr));
                bf[nb * 2][0] = r[0]; bf[nb * 2][1] = r[2];
                bf[nb * 2 + 1][0] = r[1]; bf[nb * 2 + 1][1] = r[3];
            }
            #pragma unroll
            for (int mi = 0; mi < 2; ++mi)
                #pragma unroll
                for (int ni = 0; ni < 8; ++ni)
                    mma16816(acc[mi][ni], a[mi], bf[ni]);
        }
    };

    stageA(0);
    #pragma unroll
    for (int j = 0; j < 2; ++j) {
        const __half* src = wb + (size_t)j * OUTC * CIN;
        uint32_t buf = smb + SM_B + (uint32_t)(j * 16384);
        #pragma unroll
        for (int i = 0; i < 4; ++i)
            cpasync16(buf + bdst[i], src + boff[i], 16u);
    }
    CP_COMMIT();
    CP_WAIT0();
    __syncthreads();

    for (int p = 0; p < 9; ++p) {
        if (p < 8) {
            #pragma unroll
            for (int j = 0; j < 2; ++j) {
                const int sn = 2 * p + 2 + j;
                const int hfn = sn / 9, tn = sn - hfn * 9;
                const __half* src = wb + (size_t)tn * OUTC * CIN + hfn * 64;
                uint32_t buf = smb + SM_B + (uint32_t)((sn & 3) * 16384);
                #pragma unroll
                for (int i = 0; i < 4; ++i)
                    cpasync16(buf + bdst[i], src + boff[i], 16u);
            }
            CP_COMMIT();
        }

        compute(2 * p);

        if (p == 4) {
            __syncthreads();
            stageA(64);
            CP_COMMIT();
            CP_WAIT0();
            __syncthreads();
        }

        compute(2 * p + 1);

        if (p < 8) {
            CP_WAIT0();
            __syncthreads();
        }
    }

    float* csm = (float*)(sm + SM_A);
    float* ob = out + (size_t)b * OUTC * HW;
    __syncthreads();
    #pragma unroll
    for (int mi = 0; mi < 2; ++mi) {
        const int prl = wm * 32 + mi * 16 + (lane >> 2);
        #pragma unroll
        for (int ni = 0; ni < 8; ++ni) {
            const int ocl = wn * 64 + ni * 8 + (lane & 3) * 2;
            csm[ocl * 132 + prl]           = acc[mi][ni][0];
            csm[(ocl + 1) * 132 + prl]     = acc[mi][ni][1];
            csm[ocl * 132 + prl + 8]       = acc[mi][ni][2];
            csm[(ocl + 1) * 132 + prl + 8] = acc[mi][ni][3];
        }
    }
    __syncthreads();
    #pragma unroll
    for (int i = 0; i < 16; ++i) {
        int idx = tid + i * 256;
        int ocl = idx >> 5, px4 = idx & 31;
        int pix = pbase + px4 * 4;
        if (pix < HW) {
            float4 v = *(float4*)&csm[ocl * 132 + px4 * 4];
            float bb = bias[ocl];
            v.x += bb; v.y += bb; v.z += bb; v.w += bb;
            *(float4*)&ob[(size_t)ocl * HW + pix] = v;
        }
    }
}

extern "C" void kernel_launch(void* const* d_in, const int* in_sizes, int n_in,
                              void* d_out, int out_size) {
    const float* x     = (const float*)d_in[0];
    const float* cw    = (const float*)d_in[1];
    const float* cb    = (const float*)d_in[2];
    const float* dw    = (const float*)d_in[3];
    const float* db    = (const float*)d_in[4];
    const float* fc1_w = (const float*)d_in[5];
    const float* fc2_w = (const float*)d_in[6];
    float* out = (float*)d_out;

    cudaFuncSetAttribute(conv_kernel, cudaFuncAttributeMaxDynamicSharedMemorySize, SM_TOT);

    convx_kernel<<<dim3(NPBLK, 2, BATCH), 256>>>(x);
    mlp_kernel<<<BATCH, 128>>>(fc1_w, fc2_w);
    aggw_kernel<<<OUTC, 256>>>(cw, dw);
    conv_kernel<<<dim3(NPB, BATCH), 256, SM_TOT>>>(cb, db, out);
}